// round 1
// baseline (speedup 1.0000x reference)
#include <cuda_runtime.h>
#include <cstdint>

#define Bn   8
#define Cc   64
#define Hh   256
#define Ww   256
#define HW   (Hh*Ww)
#define CIN  65
#define CMID 32

typedef unsigned long long ull;

// ---------------- packed f32x2 helpers ----------------
__device__ __forceinline__ ull pack2(float a, float b) {
    ull r; asm("mov.b64 %0,{%1,%2};" : "=l"(r) : "f"(a), "f"(b)); return r;
}
__device__ __forceinline__ void unpack2(ull v, float& a, float& b) {
    asm("mov.b64 {%0,%1},%2;" : "=f"(a), "=f"(b) : "l"(v));
}
__device__ __forceinline__ void fma2(ull& d, ull a, ull b) {
    asm("fma.rn.f32x2 %0,%1,%2,%0;" : "+l"(d) : "l"(a), "l"(b));
}

// ---------------- device scratch (static, no allocations) ----------------
__device__ float2 g_Wp[CIN * 9 * 16];   // conv weights, BN1-folded, [c*9+k][opair]
__device__ float  g_b1[CMID];           // BN1 shift (acts as conv bias)
__device__ float2 g_W2p[Cc * 32];       // w_enh, BN2-folded, [c][opair]
__device__ float  g_sh2[Cc];            // BN2 shift
__device__ int2   g_offs[Bn * HW];      // per-pixel bilinear row offsets
__device__ float4 g_cw[Bn * HW];        // per-pixel bilinear corner weights

// ---------------- stage 0: fold BN into weights ----------------
__global__ void k_prep(const float* __restrict__ w1,
                       const float* __restrict__ g1, const float* __restrict__ b1,
                       const float* __restrict__ m1, const float* __restrict__ v1,
                       const float* __restrict__ wenh,
                       const float* __restrict__ g2, const float* __restrict__ b2,
                       const float* __restrict__ m2, const float* __restrict__ v2)
{
    __shared__ float inv1s[CMID], inv2s[Cc];
    int t = threadIdx.x;
    if (t < CMID) {
        float inv = g1[t] * rsqrtf(v1[t] + 1e-5f);
        inv1s[t] = inv;
        g_b1[t] = b1[t] - m1[t] * inv;
    }
    if (t < Cc) {
        float inv = g2[t] * rsqrtf(v2[t] + 1e-5f);
        inv2s[t] = inv;
        g_sh2[t] = b2[t] - m2[t] * inv;
    }
    __syncthreads();
    for (int i = t; i < CIN * 9 * 16; i += blockDim.x) {
        int op = i & 15, ck = i >> 4;
        int c = ck / 9, k = ck - c * 9;
        int o0 = 2 * op, o1 = o0 + 1;
        g_Wp[i] = make_float2(w1[(o0 * CIN + c) * 9 + k] * inv1s[o0],
                              w1[(o1 * CIN + c) * 9 + k] * inv1s[o1]);
    }
    for (int i = t; i < Cc * 32; i += blockDim.x) {
        int op = i & 31, c = i >> 5;
        int o0 = 2 * op, o1 = o0 + 1;
        g_W2p[i] = make_float2(wenh[o0 * Cc + c] * inv2s[o0],
                               wenh[o1 * Cc + c] * inv2s[o1]);
    }
}

// ---------------- stage 1: conv3x3 + SiLU + offset proj + grid build ----------------
// tile 64x16 px, 256 threads; thread = (tx 0..63, tq 0..3) owns 4 consecutive rows
#define NW2  (9360)              // CIN*9*16 weight pairs
#define NT2  (66 * 18)           // tile (64+2)x(16+2)
#define SMEM2 ((NW2 + NT2) * (int)sizeof(float2))

__global__ void __launch_bounds__(256, 1) k_offset(
    const float* __restrict__ x, const float* __restrict__ hm,
    const float* __restrict__ w_off2, const float* __restrict__ b_off2)
{
    extern __shared__ float2 sm[];
    float2* sW = sm;        // NW2
    float2* sT = sm + NW2;  // NT2
    __shared__ float sB1[CMID], sW2[2 * CMID], sB2[2];

    const int b   = blockIdx.z;
    const int tx0 = blockIdx.x * 64, ty0 = blockIdx.y * 16;
    const int t   = threadIdx.x;

    for (int i = t; i < NW2; i += 256) sW[i] = g_Wp[i];
    if (t < 2 * CMID) sW2[t] = w_off2[t];
    if (t < CMID)     sB1[t] = g_b1[t];
    if (t < 2)        sB2[t] = b_off2[t];

    const int tx  = t & 63;
    const int tq  = t >> 6;
    const int px  = tx0 + tx;
    const int py0 = ty0 + tq * 4;

    ull acc[16][4];
#pragma unroll
    for (int op = 0; op < 16; op++)
#pragma unroll
        for (int i = 0; i < 4; i++) acc[op][i] = 0ull;

    __syncthreads();

    for (int c = 0; c < CIN; c++) {
        const float* plane = (c < Cc) ? x + (size_t)(b * Cc + c) * HW
                                      : hm + (size_t)b * HW;
        __syncthreads();
        for (int i = t; i < NT2; i += 256) {
            int r = i / 66, col = i - r * 66;
            int gy = ty0 - 1 + r, gx2 = tx0 - 1 + col;
            float v = 0.f;
            if ((unsigned)gy < (unsigned)Hh && (unsigned)gx2 < (unsigned)Ww)
                v = __ldg(plane + gy * Ww + gx2);
            sT[i] = make_float2(v, v);
        }
        __syncthreads();

        ull pix[6][3];
#pragma unroll
        for (int r = 0; r < 6; r++)
#pragma unroll
            for (int cx = 0; cx < 3; cx++)
                pix[r][cx] = *reinterpret_cast<const ull*>(&sT[(tq * 4 + r) * 66 + tx + cx]);

        const float2* wc = sW + c * 9 * 16;
#pragma unroll
        for (int op = 0; op < 16; op++) {
            ull w[9];
#pragma unroll
            for (int k = 0; k < 9; k++)
                w[k] = *reinterpret_cast<const ull*>(&wc[k * 16 + op]);
#pragma unroll
            for (int i = 0; i < 4; i++) {
#pragma unroll
                for (int ky = 0; ky < 3; ky++) {
#pragma unroll
                    for (int kx = 0; kx < 3; kx++)
                        fma2(acc[op][i], w[ky * 3 + kx], pix[i + ky][kx]);
                }
            }
        }
    }

    // epilogue: SiLU -> 2-channel projection -> grid -> bilinear metadata
    // (heatmap channel c=64 is still resident in sT)
#pragma unroll
    for (int i = 0; i < 4; i++) {
        float o0 = sB2[0], o1 = sB2[1];
#pragma unroll
        for (int op = 0; op < 16; op++) {
            float a, bb; unpack2(acc[op][i], a, bb);
            a  += sB1[2 * op];
            bb += sB1[2 * op + 1];
            float sa = __fdividef(a,  1.f + __expf(-a));
            float sb = __fdividef(bb, 1.f + __expf(-bb));
            o0 += sW2[2 * op] * sa + sW2[2 * op + 1] * sb;
            o1 += sW2[CMID + 2 * op] * sa + sW2[CMID + 2 * op + 1] * sb;
        }
        int y = py0 + i;
        float hmv = sT[(tq * 4 + i + 1) * 66 + tx + 1].x;

        float gxv = fminf(fmaxf(px * (2.f / 255.f) - 1.f + o0 * 0.1f * hmv, -1.f), 1.f);
        float gyv = fminf(fmaxf(y  * (2.f / 255.f) - 1.f + o1 * 0.1f * hmv, -1.f), 1.f);
        float ix = (gxv + 1.f) * 127.5f;
        float iy = (gyv + 1.f) * 127.5f;
        float x0f = floorf(ix), y0f = floorf(iy);
        float wx = ix - x0f, wy = iy - y0f;
        int xi0 = min(max((int)x0f, 0), Ww - 1);
        int xi1 = min(max((int)x0f + 1, 0), Ww - 1);
        int yi0 = min(max((int)y0f, 0), Hh - 1);
        int yi1 = min(max((int)y0f + 1, 0), Hh - 1);
        int xa = min(xi0, Ww - 2);
        // lane weights for float-pair at [xa, xa+1]
        float lx0 = (xi0 == xa     ? (1.f - wx) : 0.f) + (xi1 == xa     ? wx : 0.f);
        float lx1 = (xi0 == xa + 1 ? (1.f - wx) : 0.f) + (xi1 == xa + 1 ? wx : 0.f);
        float wy0 = 1.f - wy;

        int idx = b * HW + y * Ww + px;
        g_offs[idx] = make_int2(yi0 * Ww + xa, yi1 * Ww + xa);
        g_cw[idx]   = make_float4(wy0 * lx0, wy0 * lx1, wy * lx0, wy * lx1);
    }
}

// ---------------- stage 2: grid-sample + 64x64 GEMM + BN2/SiLU + residual ----------------
// 128 threads/block, 2 px/thread (p and p+128), 256 px/block
__global__ void __launch_bounds__(128) k_enh(
    const float* __restrict__ x, const float* __restrict__ gamma_p,
    float* __restrict__ out)
{
    __shared__ float2 sW2[Cc * 32];
    __shared__ float  sSh[Cc];
    __shared__ float  sG;

    const int t = threadIdx.x;
    for (int i = t; i < Cc * 32; i += 128) sW2[i] = g_W2p[i];
    if (t < Cc) sSh[t] = g_sh2[t];
    if (t == 0) sG = __ldg(gamma_p);

    const int b  = blockIdx.y;
    const int p0 = blockIdx.x * 256 + t;
    const int p1 = p0 + 128;

    const int2   of0 = g_offs[b * HW + p0];
    const int2   of1 = g_offs[b * HW + p1];
    const float4 cw0 = g_cw[b * HW + p0];
    const float4 cw1 = g_cw[b * HW + p1];

    __syncthreads();

    ull acc[32][2];
#pragma unroll
    for (int op = 0; op < 32; op++) { acc[op][0] = 0ull; acc[op][1] = 0ull; }

    const float* xb = x + (size_t)b * Cc * HW;

    for (int c = 0; c < Cc; c++) {
        const float* plane = xb + (size_t)c * HW;
        float a0 = __ldg(plane + of0.x),     b0 = __ldg(plane + of0.x + 1);
        float c0 = __ldg(plane + of0.y),     d0 = __ldg(plane + of0.y + 1);
        float a1 = __ldg(plane + of1.x),     b1v = __ldg(plane + of1.x + 1);
        float c1 = __ldg(plane + of1.y),     d1 = __ldg(plane + of1.y + 1);
        float r0 = cw0.x * a0 + cw0.y * b0 + cw0.z * c0 + cw0.w * d0;
        float r1 = cw1.x * a1 + cw1.y * b1v + cw1.z * c1 + cw1.w * d1;
        ull rr0 = pack2(r0, r0);
        ull rr1 = pack2(r1, r1);
        const float2* wrow = sW2 + c * 32;
#pragma unroll
        for (int op = 0; op < 32; op++) {
            ull w = *reinterpret_cast<const ull*>(&wrow[op]);
            fma2(acc[op][0], w, rr0);
            fma2(acc[op][1], w, rr1);
        }
    }

    float* ob = out + (size_t)b * Cc * HW;
    float g = sG;
#pragma unroll
    for (int op = 0; op < 32; op++) {
        int o0 = 2 * op, o1 = o0 + 1;
        float s0 = sSh[o0], s1 = sSh[o1];
        float za, zb, zc, zd;
        unpack2(acc[op][0], za, zb);   // pixel p0, channels o0,o1
        unpack2(acc[op][1], zc, zd);   // pixel p1, channels o0,o1
        za += s0; zb += s1; zc += s0; zd += s1;
        float ea = __fdividef(za, 1.f + __expf(-za));
        float eb = __fdividef(zb, 1.f + __expf(-zb));
        float ec = __fdividef(zc, 1.f + __expf(-zc));
        float ed = __fdividef(zd, 1.f + __expf(-zd));
        size_t b0i = (size_t)o0 * HW, b1i = (size_t)o1 * HW;
        ob[b0i + p0] = __ldg(xb + b0i + p0) + g * ea;
        ob[b1i + p0] = __ldg(xb + b1i + p0) + g * eb;
        ob[b0i + p1] = __ldg(xb + b0i + p1) + g * ec;
        ob[b1i + p1] = __ldg(xb + b1i + p1) + g * ed;
    }
}

// ---------------- launch ----------------
extern "C" void kernel_launch(void* const* d_in, const int* in_sizes, int n_in,
                              void* d_out, int out_size)
{
    const float* x      = (const float*)d_in[0];
    const float* hm     = (const float*)d_in[1];
    const float* w1     = (const float*)d_in[2];
    const float* g1     = (const float*)d_in[3];
    const float* b1     = (const float*)d_in[4];
    const float* m1     = (const float*)d_in[5];
    const float* v1     = (const float*)d_in[6];
    const float* w_off2 = (const float*)d_in[7];
    const float* b_off2 = (const float*)d_in[8];
    const float* wenh   = (const float*)d_in[9];
    const float* g2     = (const float*)d_in[10];
    const float* b2     = (const float*)d_in[11];
    const float* m2     = (const float*)d_in[12];
    const float* v2     = (const float*)d_in[13];
    const float* gamma  = (const float*)d_in[14];
    float* out = (float*)d_out;

    (void)in_sizes; (void)n_in; (void)out_size;

    // opt-in to >48KB dynamic smem (idempotent; safe pre-capture and during)
    cudaFuncSetAttribute(k_offset, cudaFuncAttributeMaxDynamicSharedMemorySize, SMEM2);

    k_prep<<<1, 256>>>(w1, g1, b1, m1, v1, wenh, g2, b2, m2, v2);

    dim3 grid2(Ww / 64, Hh / 16, Bn);
    k_offset<<<grid2, 256, SMEM2>>>(x, hm, w_off2, b_off2);

    dim3 grid3(HW / 256, Bn);
    k_enh<<<grid3, 128>>>(x, gamma, out);
}

// round 2
// speedup vs baseline: 1.3230x; 1.3230x over previous
#include <cuda_runtime.h>
#include <cstdint>

#define Bn   8
#define Cc   64
#define Hh   256
#define Ww   256
#define HW   (Hh*Ww)
#define CIN  65
#define CMID 32

typedef unsigned long long ull;

// ---------------- packed f32x2 helpers ----------------
__device__ __forceinline__ ull pack2(float a, float b) {
    ull r; asm("mov.b64 %0,{%1,%2};" : "=l"(r) : "f"(a), "f"(b)); return r;
}
__device__ __forceinline__ void unpack2(ull v, float& a, float& b) {
    asm("mov.b64 {%0,%1},%2;" : "=f"(a), "=f"(b) : "l"(v));
}
__device__ __forceinline__ void fma2(ull& d, ull a, ull b) {
    asm("fma.rn.f32x2 %0,%1,%2,%0;" : "+l"(d) : "l"(a), "l"(b));
}

// ---------------- device scratch (static, no allocations) ----------------
__device__ int2   g_offs[Bn * HW];      // per-pixel bilinear row offsets
__device__ float4 g_cw[Bn * HW];        // per-pixel bilinear corner weights

// ================= stage 1: conv3x3(BN-folded) + SiLU + offset proj + grid build =================
// tile 64x8 px, 256 threads; thread = (tx 0..63, tq 0..3) owns 2 consecutive rows.
// Double-buffered input tile; all folded conv weights staged in smem.
#define NW2  (CIN * 9 * 16)       // 9360 weight float2 pairs
#define NT2  (66 * 10)            // 660  tile elements (64+2)x(8+2)
#define SMEM2 ((NW2 + 2 * NT2) * (int)sizeof(float2))

__global__ void __launch_bounds__(256, 1) k_offset(
    const float* __restrict__ x, const float* __restrict__ hm,
    const float* __restrict__ w1,
    const float* __restrict__ g1, const float* __restrict__ b1,
    const float* __restrict__ m1, const float* __restrict__ v1,
    const float* __restrict__ w_off2, const float* __restrict__ b_off2)
{
    extern __shared__ float2 sm[];
    float2* sW  = sm;               // NW2
    float2* sT0 = sm + NW2;         // NT2
    float2* sT1 = sm + NW2 + NT2;   // NT2
    __shared__ float sInv1[CMID], sB1[CMID], sW2[2 * CMID], sB2[2];

    const int b   = blockIdx.z;
    const int tx0 = blockIdx.x * 64, ty0 = blockIdx.y * 8;
    const int t   = threadIdx.x;

    // --- fold BN1 on the fly ---
    if (t < CMID) {
        float inv = g1[t] * rsqrtf(v1[t] + 1e-5f);
        sInv1[t] = inv;
        sB1[t]   = b1[t] - m1[t] * inv;
    }
    if (t < 2 * CMID) sW2[t] = w_off2[t];
    if (t < 2)        sB2[t] = b_off2[t];
    __syncthreads();

    // --- stage folded weights: layout [c][k][opair] ---
    for (int i = t; i < NW2; i += 256) {
        int op = i & 15, ck = i >> 4;
        int c = ck / 9, k = ck - c * 9;
        int o0 = 2 * op, o1 = o0 + 1;
        sW[i] = make_float2(__ldg(w1 + (o0 * CIN + c) * 9 + k) * sInv1[o0],
                            __ldg(w1 + (o1 * CIN + c) * 9 + k) * sInv1[o1]);
    }

    const int tx  = t & 63;
    const int tq  = t >> 6;
    const int px  = tx0 + tx;
    const int py0 = ty0 + tq * 2;

    ull acc[16][2];
#pragma unroll
    for (int op = 0; op < 16; op++) { acc[op][0] = 0ull; acc[op][1] = 0ull; }

    // --- tile prefetch machinery (<=3 elements per thread) ---
    float pre[3];
    const float* xb = x + (size_t)b * Cc * HW;
    const float* hb = hm + (size_t)b * HW;

    // load channel 0
    {
        const float* plane = xb;
#pragma unroll
        for (int j = 0; j < 3; j++) {
            int i = t + j * 256;
            pre[j] = 0.f;
            if (i < NT2) {
                int r = i / 66, col = i - r * 66;
                int gy = ty0 - 1 + r, gx2 = tx0 - 1 + col;
                if ((unsigned)gy < (unsigned)Hh && (unsigned)gx2 < (unsigned)Ww)
                    pre[j] = __ldg(plane + gy * Ww + gx2);
            }
        }
#pragma unroll
        for (int j = 0; j < 3; j++) {
            int i = t + j * 256;
            if (i < NT2) sT0[i] = make_float2(pre[j], pre[j]);
        }
    }

    for (int c = 0; c < CIN; c++) {
        __syncthreads();   // (c==0: weights+tile0 ready; else: tile c stores done)

        // prefetch channel c+1 into registers (latency hidden behind compute)
        if (c + 1 < CIN) {
            const float* plane = (c + 1 < Cc) ? xb + (size_t)(c + 1) * HW : hb;
#pragma unroll
            for (int j = 0; j < 3; j++) {
                int i = t + j * 256;
                pre[j] = 0.f;
                if (i < NT2) {
                    int r = i / 66, col = i - r * 66;
                    int gy = ty0 - 1 + r, gx2 = tx0 - 1 + col;
                    if ((unsigned)gy < (unsigned)Hh && (unsigned)gx2 < (unsigned)Ww)
                        pre[j] = __ldg(plane + gy * Ww + gx2);
                }
            }
        }

        const float2* cur = (c & 1) ? sT1 : sT0;

        ull pix[4][3];
#pragma unroll
        for (int r = 0; r < 4; r++)
#pragma unroll
            for (int cx = 0; cx < 3; cx++)
                pix[r][cx] = *reinterpret_cast<const ull*>(&cur[(tq * 2 + r) * 66 + tx + cx]);

        const float2* wc = sW + c * 144;
#pragma unroll
        for (int op = 0; op < 16; op++) {
            ull w[9];
#pragma unroll
            for (int k = 0; k < 9; k++)
                w[k] = *reinterpret_cast<const ull*>(&wc[k * 16 + op]);
#pragma unroll
            for (int i = 0; i < 2; i++)
#pragma unroll
                for (int ky = 0; ky < 3; ky++)
#pragma unroll
                    for (int kx = 0; kx < 3; kx++)
                        fma2(acc[op][i], w[ky * 3 + kx], pix[i + ky][kx]);
        }

        // store prefetched tile into the other buffer
        if (c + 1 < CIN) {
            float2* nxt = (c & 1) ? sT0 : sT1;
#pragma unroll
            for (int j = 0; j < 3; j++) {
                int i = t + j * 256;
                if (i < NT2) nxt[i] = make_float2(pre[j], pre[j]);
            }
        }
    }

    // heatmap tile (c=64) lives in buffer parity (64&1)==0 -> sT0
    const float2* hmT = sT0;

    // --- epilogue: SiLU -> 2-channel projection -> grid -> bilinear metadata ---
#pragma unroll
    for (int i = 0; i < 2; i++) {
        float o0 = sB2[0], o1 = sB2[1];
#pragma unroll
        for (int op = 0; op < 16; op++) {
            float a, bb; unpack2(acc[op][i], a, bb);
            a  += sB1[2 * op];
            bb += sB1[2 * op + 1];
            float sa = __fdividef(a,  1.f + __expf(-a));
            float sb = __fdividef(bb, 1.f + __expf(-bb));
            o0 += sW2[2 * op] * sa + sW2[2 * op + 1] * sb;
            o1 += sW2[CMID + 2 * op] * sa + sW2[CMID + 2 * op + 1] * sb;
        }
        int y = py0 + i;
        float hmv = hmT[(tq * 2 + i + 1) * 66 + tx + 1].x;

        float gxv = fminf(fmaxf(px * (2.f / 255.f) - 1.f + o0 * 0.1f * hmv, -1.f), 1.f);
        float gyv = fminf(fmaxf(y  * (2.f / 255.f) - 1.f + o1 * 0.1f * hmv, -1.f), 1.f);
        float ix = (gxv + 1.f) * 127.5f;
        float iy = (gyv + 1.f) * 127.5f;
        float x0f = floorf(ix), y0f = floorf(iy);
        float wx = ix - x0f, wy = iy - y0f;
        int xi0 = min(max((int)x0f, 0), Ww - 1);
        int xi1 = min(max((int)x0f + 1, 0), Ww - 1);
        int yi0 = min(max((int)y0f, 0), Hh - 1);
        int yi1 = min(max((int)y0f + 1, 0), Hh - 1);
        int xa = min(xi0, Ww - 2);
        float lx0 = (xi0 == xa     ? (1.f - wx) : 0.f) + (xi1 == xa     ? wx : 0.f);
        float lx1 = (xi0 == xa + 1 ? (1.f - wx) : 0.f) + (xi1 == xa + 1 ? wx : 0.f);
        float wy0 = 1.f - wy;

        int idx = b * HW + y * Ww + px;
        g_offs[idx] = make_int2(yi0 * Ww + xa, yi1 * Ww + xa);
        g_cw[idx]   = make_float4(wy0 * lx0, wy0 * lx1, wy * lx0, wy * lx1);
    }
}

// ================= stage 2: grid-sample + 64x64 GEMM(BN2-folded) + SiLU + residual =================
// 128 threads/block, 2 px/thread (p, p+128); software-pipelined gathers; LDS.128 weights.
__global__ void __launch_bounds__(128) k_enh(
    const float* __restrict__ x,
    const float* __restrict__ wenh,
    const float* __restrict__ g2, const float* __restrict__ b2,
    const float* __restrict__ m2, const float* __restrict__ v2,
    const float* __restrict__ gamma_p,
    float* __restrict__ out)
{
    __shared__ __align__(16) float2 sW2[Cc * 32];   // [c][opair], BN2-folded
    __shared__ float sInv2[Cc], sSh[Cc];
    __shared__ float sG;

    const int t = threadIdx.x;
    if (t < Cc) {
        float inv = g2[t] * rsqrtf(v2[t] + 1e-5f);
        sInv2[t] = inv;
        sSh[t]   = b2[t] - m2[t] * inv;
    }
    if (t == 0) sG = __ldg(gamma_p);
    __syncthreads();
    for (int i = t; i < Cc * 32; i += 128) {
        int op = i & 31, c = i >> 5;
        int o0 = 2 * op, o1 = o0 + 1;
        sW2[i] = make_float2(__ldg(wenh + o0 * Cc + c) * sInv2[o0],
                             __ldg(wenh + o1 * Cc + c) * sInv2[o1]);
    }

    const int b  = blockIdx.y;
    const int p0 = blockIdx.x * 256 + t;
    const int p1 = p0 + 128;

    const int2   of0 = g_offs[b * HW + p0];
    const int2   of1 = g_offs[b * HW + p1];
    const float4 cw0 = g_cw[b * HW + p0];
    const float4 cw1 = g_cw[b * HW + p1];

    __syncthreads();

    ull acc[32][2];
#pragma unroll
    for (int op = 0; op < 32; op++) { acc[op][0] = 0ull; acc[op][1] = 0ull; }

    const float* xb = x + (size_t)b * Cc * HW;

    float cur[8], nxt[8];
    {
        const float* plane = xb;
        cur[0] = __ldg(plane + of0.x); cur[1] = __ldg(plane + of0.x + 1);
        cur[2] = __ldg(plane + of0.y); cur[3] = __ldg(plane + of0.y + 1);
        cur[4] = __ldg(plane + of1.x); cur[5] = __ldg(plane + of1.x + 1);
        cur[6] = __ldg(plane + of1.y); cur[7] = __ldg(plane + of1.y + 1);
    }

    for (int c = 0; c < Cc; c++) {
        if (c + 1 < Cc) {
            const float* plane = xb + (size_t)(c + 1) * HW;
            nxt[0] = __ldg(plane + of0.x); nxt[1] = __ldg(plane + of0.x + 1);
            nxt[2] = __ldg(plane + of0.y); nxt[3] = __ldg(plane + of0.y + 1);
            nxt[4] = __ldg(plane + of1.x); nxt[5] = __ldg(plane + of1.x + 1);
            nxt[6] = __ldg(plane + of1.y); nxt[7] = __ldg(plane + of1.y + 1);
        }

        float r0 = cw0.x * cur[0] + cw0.y * cur[1] + cw0.z * cur[2] + cw0.w * cur[3];
        float r1 = cw1.x * cur[4] + cw1.y * cur[5] + cw1.z * cur[6] + cw1.w * cur[7];
        ull rr0 = pack2(r0, r0);
        ull rr1 = pack2(r1, r1);

        const ulonglong2* wrow = reinterpret_cast<const ulonglong2*>(sW2 + c * 32);
#pragma unroll
        for (int q = 0; q < 16; q++) {
            ulonglong2 w = wrow[q];
            fma2(acc[2 * q][0],     w.x, rr0);
            fma2(acc[2 * q][1],     w.x, rr1);
            fma2(acc[2 * q + 1][0], w.y, rr0);
            fma2(acc[2 * q + 1][1], w.y, rr1);
        }

#pragma unroll
        for (int j = 0; j < 8; j++) cur[j] = nxt[j];
    }

    float* ob = out + (size_t)b * Cc * HW;
    float g = sG;
#pragma unroll
    for (int op = 0; op < 32; op++) {
        int o0 = 2 * op, o1 = o0 + 1;
        float s0 = sSh[o0], s1 = sSh[o1];
        float za, zb, zc, zd;
        unpack2(acc[op][0], za, zb);   // pixel p0, channels o0,o1
        unpack2(acc[op][1], zc, zd);   // pixel p1, channels o0,o1
        za += s0; zb += s1; zc += s0; zd += s1;
        float ea = __fdividef(za, 1.f + __expf(-za));
        float eb = __fdividef(zb, 1.f + __expf(-zb));
        float ec = __fdividef(zc, 1.f + __expf(-zc));
        float ed = __fdividef(zd, 1.f + __expf(-zd));
        size_t b0i = (size_t)o0 * HW, b1i = (size_t)o1 * HW;
        ob[b0i + p0] = __ldg(xb + b0i + p0) + g * ea;
        ob[b1i + p0] = __ldg(xb + b1i + p0) + g * eb;
        ob[b0i + p1] = __ldg(xb + b0i + p1) + g * ec;
        ob[b1i + p1] = __ldg(xb + b1i + p1) + g * ed;
    }
}

// ---------------- launch ----------------
extern "C" void kernel_launch(void* const* d_in, const int* in_sizes, int n_in,
                              void* d_out, int out_size)
{
    const float* x      = (const float*)d_in[0];
    const float* hm     = (const float*)d_in[1];
    const float* w1     = (const float*)d_in[2];
    const float* g1     = (const float*)d_in[3];
    const float* b1     = (const float*)d_in[4];
    const float* m1     = (const float*)d_in[5];
    const float* v1     = (const float*)d_in[6];
    const float* w_off2 = (const float*)d_in[7];
    const float* b_off2 = (const float*)d_in[8];
    const float* wenh   = (const float*)d_in[9];
    const float* g2     = (const float*)d_in[10];
    const float* b2     = (const float*)d_in[11];
    const float* m2     = (const float*)d_in[12];
    const float* v2     = (const float*)d_in[13];
    const float* gamma  = (const float*)d_in[14];
    float* out = (float*)d_out;

    (void)in_sizes; (void)n_in; (void)out_size;

    cudaFuncSetAttribute(k_offset, cudaFuncAttributeMaxDynamicSharedMemorySize, SMEM2);

    dim3 grid2(Ww / 64, Hh / 8, Bn);
    k_offset<<<grid2, 256, SMEM2>>>(x, hm, w1, g1, b1, m1, v1, w_off2, b_off2);

    dim3 grid3(HW / 256, Bn);
    k_enh<<<grid3, 128>>>(x, wenh, g2, b2, m2, v2, gamma, out);
}